// round 2
// baseline (speedup 1.0000x reference)
#include <cuda_runtime.h>
#include <math.h>

#define NN   20000
#define E1C  100000
#define E2C  100000
#define NEF  220000            /* kept edges: E1 + N (first E3d half) + E2 */
#define HN   (NN*128)
#define CUTV 6.0f
#define PI_F 3.14159265358979f
#define XSL  192

/* ---------- persistent device scratch (no runtime allocation) ---------- */
__device__ float g_WcT[256*128];     /* (W_phi1[:, :128] @ W_i)^T     [k][p] */
__device__ float g_Wc2dT[64*128];    /* (W_phi1[:,128:256] @ W_e2d)^T [k][p] */
__device__ float g_WcrbfT[64*128];   /* (W_phi1[:,128:256] @ W_rbf)^T [k][p] */
__device__ float g_etb[3*128];       /* b_phi1 + W_phi1[:,256:288] @ et[t]   */
__device__ float g_cvec[128];        /* virt @ (W1a@W_i)[:,128:].T           */
__device__ float g_nproj[(size_t)2*NN*128];
__device__ unsigned char g_mask[NN];

/* ---------- precompute folded weights ---------- */
__global__ void k_pre1(const float* __restrict__ W_i, const float* __restrict__ W_phi1,
                       const float* __restrict__ b_phi1, const float* __restrict__ W_e2d,
                       const float* __restrict__ W_rbf, const float* __restrict__ ET)
{
    int idx = blockIdx.x*256 + threadIdx.x;
    if (idx < NN) g_mask[idx] = 0;
    if (idx < 32768) {
        int k = idx >> 7, p = idx & 127;
        float s = 0.f;
        #pragma unroll 4
        for (int j = 0; j < 128; j++) s += W_phi1[p*288 + j] * W_i[j*256 + k];
        g_WcT[idx] = s;
    } else if (idx < 40960) {
        int i = idx - 32768; int k = i >> 7, p = i & 127;
        float s = 0.f;
        #pragma unroll 4
        for (int j = 0; j < 128; j++) s += W_phi1[p*288 + 128 + j] * W_e2d[j*64 + k];
        g_Wc2dT[i] = s;
    } else if (idx < 49152) {
        int i = idx - 40960; int k = i >> 7, p = i & 127;
        float s = 0.f;
        #pragma unroll 4
        for (int j = 0; j < 128; j++) s += W_phi1[p*288 + 128 + j] * W_rbf[j*64 + k];
        g_WcrbfT[i] = s;
    } else if (idx < 49536) {
        int i = idx - 49152; int tt = i >> 7, p = i & 127;
        float s = b_phi1[p];
        #pragma unroll
        for (int l = 0; l < 32; l++) s += W_phi1[p*288 + 256 + l] * ET[tt*32 + l];
        g_etb[i] = s;
    }
}

__global__ void k_pre2(const float* __restrict__ W_i, const float* __restrict__ W_phi1,
                       const float* __restrict__ virt)
{
    __shared__ float u[128];
    int t = threadIdx.x;
    float s = 0.f;
    #pragma unroll 4
    for (int j = 0; j < 128; j++) s += W_i[t*256 + 128 + j] * virt[j];
    u[t] = s;
    __syncthreads();
    float c = 0.f;
    #pragma unroll 4
    for (int q = 0; q < 128; q++) c += W_phi1[t*288 + q] * u[q];
    g_cvec[t] = c;
}

__global__ void k_maskset(const int* __restrict__ Edist_idx)
{
    int idx = blockIdx.x*256 + threadIdx.x;
    if (idx < 2*E2C) g_mask[Edist_idx[idx]] = 1;
}

/* ---------- node projection: nproj = nodes @ W1a.T (both halves) ---------- */
__global__ void __launch_bounds__(128) k_nproj(const float* __restrict__ H,
                                               const float* __restrict__ H2d)
{
    __shared__ float hx[16*128];
    __shared__ float h2[16*128];
    int t = threadIdx.x;
    int i0 = blockIdx.x * 16;
    #pragma unroll
    for (int it = 0; it < 16; it++) {
        int idx = t + it*128;
        int nd = idx >> 7, p = idx & 127;
        hx[idx] = H  [(size_t)(i0+nd)*128 + p];
        h2[idx] = H2d[(size_t)(i0+nd)*128 + p];
    }
    __syncthreads();
    float a1[16], a2[16];
    #pragma unroll
    for (int nd = 0; nd < 16; nd++) { a1[nd] = 0.f; a2[nd] = 0.f; }
    for (int kk = 0; kk < 128; kk += 4) {
        float w0 = g_WcT[(kk+0)*128+t], w1 = g_WcT[(kk+1)*128+t];
        float w2 = g_WcT[(kk+2)*128+t], w3 = g_WcT[(kk+3)*128+t];
        float v0 = g_WcT[(128+kk+0)*128+t], v1 = g_WcT[(128+kk+1)*128+t];
        float v2 = g_WcT[(128+kk+2)*128+t], v3 = g_WcT[(128+kk+3)*128+t];
        #pragma unroll
        for (int nd = 0; nd < 16; nd++) {
            float4 f = *(const float4*)&hx[nd*128 + kk];
            a1[nd] += f.x*w0 + f.y*w1 + f.z*w2 + f.w*w3;
            float4 g = *(const float4*)&h2[nd*128 + kk];
            a2[nd] += g.x*v0 + g.y*v1 + g.z*v2 + g.w*v3;
        }
    }
    float cv = g_cvec[t];
    #pragma unroll
    for (int nd = 0; nd < 16; nd++) {
        g_nproj[(size_t)(i0+nd)*128 + t]      = a1[nd] + a2[nd];
        g_nproj[(size_t)(NN+i0+nd)*128 + t]   = a1[nd] + cv;
    }
}

/* ---------- fused per-edge kernel ---------- */
__global__ void __launch_bounds__(128) k_edge(
    const int* __restrict__ E2d_idx, const float* __restrict__ E2d_feat,
    const int* __restrict__ Edist_idx, const float* __restrict__ Edist_val,
    const float* __restrict__ Z, const float* __restrict__ Z3d,
    const float* __restrict__ V,
    const float* __restrict__ W_phi2, const float* __restrict__ b_phi2,
    const float* __restrict__ W_msg, const float* __restrict__ b_msg,
    float* __restrict__ out)
{
    extern __shared__ float sm[];
    float* xs    = sm;                      /* 32 x 192                     */
    float* ws    = sm + 32*XSL;             /* 64 x 129 (padded)            */
    int*   srow  = (int*)(ws + 64*129);     /* 32                           */
    int*   scol  = srow + 32;               /* 32                           */
    float* sdist = (float*)(scol + 32);     /* 32                           */
    float* senvd = sdist + 32;              /* 32                           */
    float* sdval = senvd + 32;              /* 32                           */
    float* senv2 = sdval + 32;              /* 32                           */
    float* sunit = senv2 + 32;              /* 32 x 3                       */

    int t = threadIdx.x;
    int base = blockIdx.x * 32;
    int type = (base < E1C) ? 0 : (base < E1C + NN ? 1 : 2);

    /* --- edge metadata + geometry (warp 0) --- */
    if (t < 32) {
        int eg = base + t;
        int row, col; float dval = 0.f;
        if (type == 0)      { row = E2d_idx[eg]; col = E2d_idx[E1C + eg]; }
        else if (type == 1) { int i = eg - E1C; row = i; col = NN + i; }
        else                { int j = eg - E1C - NN; row = Edist_idx[j];
                              col = Edist_idx[E2C + j]; dval = Edist_val[j]; }
        srow[t] = row; scol[t] = col; sdval[t] = dval;
        float zr0 = Z[row*3+0], zr1 = Z[row*3+1], zr2 = Z[row*3+2];
        float zc0, zc1, zc2;
        if (col < NN) { zc0 = Z[col*3+0]; zc1 = Z[col*3+1]; zc2 = Z[col*3+2]; }
        else { int c2 = col - NN; zc0 = Z3d[c2*3+0]; zc1 = Z3d[c2*3+1]; zc2 = Z3d[c2*3+2]; }
        float r0 = zr0-zc0, r1 = zr1-zc1, r2 = zr2-zc2;
        float d = sqrtf(r0*r0 + r1*r1 + r2*r2 + 1e-8f);
        sdist[t] = d;
        float inv = 1.0f / d;
        sunit[t*3+0] = r0*inv; sunit[t*3+1] = r1*inv; sunit[t*3+2] = r2*inv;
        float cl = fminf(d * (1.0f/CUTV), 1.0f);
        senvd[t] = 0.5f * (cosf(PI_F*cl) + 1.0f);
        float cl2 = fminf(fmaxf(dval * (1.0f/CUTV), 0.f), 1.0f);
        senv2[t] = 0.5f * (cosf(PI_F*cl2) + 1.0f);
    }
    /* --- type-specific K-weight into shared (types 0,2) --- */
    if (type == 0) {
        #pragma unroll 8
        for (int it = 0; it < 64; it++) {
            int idx = t + it*128; int k = idx >> 7, p = idx & 127;
            ws[k*129 + p] = g_Wc2dT[idx];
        }
    } else if (type == 2) {
        #pragma unroll 8
        for (int it = 0; it < 64; it++) {
            int idx = t + it*128; int k = idx >> 7, p = idx & 127;
            ws[k*129 + p] = g_WcrbfT[idx];
        }
    }
    __syncthreads();

    /* --- per-edge 64-dim features into xs[e][128..191] --- */
    const float cstep = CUTV / 63.0f;
    const float i2w2  = 1.0f / (2.0f * (CUTV/64.0f) * (CUTV/64.0f));
    if (type == 0) {
        #pragma unroll
        for (int it = 0; it < 16; it++) {
            int idx = t + it*128; int e = idx & 31, k = idx >> 5;
            xs[e*XSL + 128 + k] = E2d_feat[(size_t)k*E1C + base + e];
        }
    } else if (type == 2) {
        #pragma unroll
        for (int it = 0; it < 16; it++) {
            int idx = t + it*128; int e = idx & 31, k = idx >> 5;
            float diff = sdval[e] - k*cstep;
            xs[e*XSL + 128 + k] = expf(-diff*diff*i2w2) * senv2[e];
        }
    }
    /* --- gather node projection + edge-type bias into registers --- */
    float accA[32];
    {
        float etbv = g_etb[type*128 + t];
        #pragma unroll
        for (int e = 0; e < 32; e++)
            accA[e] = g_nproj[(size_t)scol[e]*128 + t] + etbv;
    }
    __syncthreads();

    /* --- phase A GEMM: accA += feats @ Wtype^T --- */
    if (type != 1) {
        for (int kk = 0; kk < 64; kk += 4) {
            float w0 = ws[(kk+0)*129+t], w1 = ws[(kk+1)*129+t];
            float w2 = ws[(kk+2)*129+t], w3 = ws[(kk+3)*129+t];
            #pragma unroll
            for (int e = 0; e < 32; e++) {
                float4 f = *(const float4*)&xs[e*XSL + 128 + kk];
                accA[e] += f.x*w0 + f.y*w1 + f.z*w2 + f.w*w3;
            }
        }
    }
    __syncthreads();

    /* --- geometric RBF overwrites feats; silu(act) into xs[e][0..127] --- */
    #pragma unroll
    for (int it = 0; it < 16; it++) {
        int idx = t + it*128; int e = idx & 31, k = idx >> 5;
        float diff = sdist[e] - k*cstep;
        xs[e*XSL + 128 + k] = expf(-diff*diff*i2w2) * senvd[e];
    }
    #pragma unroll
    for (int e = 0; e < 32; e++) {
        float x = accA[e];
        xs[e*XSL + t] = x / (1.0f + expf(-x));
    }
    __syncthreads();

    /* --- phase C: [phi | wd] GEMMs + fused scatter --- */
    float vg[32];
    for (int qc = 0; qc < 3; qc++) {
        float bp = b_phi2[qc*128 + t];
        float bm = b_msg [qc*128 + t];
        float accP[32], accW[32];
        #pragma unroll
        for (int e = 0; e < 32; e++) { accP[e] = 0.f; accW[e] = 0.f; }

        for (int kc = 0; kc < 3; kc++) {
            __syncthreads();
            if (kc < 2) {
                #pragma unroll 8
                for (int it = 0; it < 64; it++) {
                    int idx = t + it*128; int ql = idx >> 6, kk = idx & 63;
                    ws[kk*129 + ql] = W_phi2[(size_t)(qc*128 + ql)*128 + kc*64 + kk];
                }
            } else {
                #pragma unroll 8
                for (int it = 0; it < 64; it++) {
                    int idx = t + it*128; int ql = idx >> 6, kk = idx & 63;
                    ws[kk*129 + ql] = W_msg[(size_t)(qc*128 + ql)*64 + kk];
                }
            }
            __syncthreads();
            if (kc < 2) {
                int kbase = kc * 64;
                for (int kk = 0; kk < 64; kk += 4) {
                    float w0 = ws[(kk+0)*129+t], w1 = ws[(kk+1)*129+t];
                    float w2 = ws[(kk+2)*129+t], w3 = ws[(kk+3)*129+t];
                    #pragma unroll
                    for (int e = 0; e < 32; e++) {
                        float4 f = *(const float4*)&xs[e*XSL + kbase + kk];
                        accP[e] += f.x*w0 + f.y*w1 + f.z*w2 + f.w*w3;
                    }
                }
            } else {
                for (int kk = 0; kk < 64; kk += 4) {
                    float w0 = ws[(kk+0)*129+t], w1 = ws[(kk+1)*129+t];
                    float w2 = ws[(kk+2)*129+t], w3 = ws[(kk+3)*129+t];
                    #pragma unroll
                    for (int e = 0; e < 32; e++) {
                        float4 f = *(const float4*)&xs[e*XSL + 128 + kk];
                        accW[e] += f.x*w0 + f.y*w1 + f.z*w2 + f.w*w3;
                    }
                }
            }
        }

        if (qc == 0) {
            #pragma unroll
            for (int e = 0; e < 32; e++) {
                float m = (accP[e] + bp) * (accW[e] + bm);
                atomicAdd(out + (size_t)srow[e]*128 + t, m);
            }
        } else if (qc == 1) {
            #pragma unroll
            for (int e = 0; e < 32; e++)
                vg[e] = (accP[e] + bp) * (accW[e] + bm);
        } else {
            #pragma unroll
            for (int e = 0; e < 32; e++) {
                float rg = (accP[e] + bp) * (accW[e] + bm);
                int col = scol[e], row = srow[e];
                float v0 = 0.f, v1 = 0.f, v2 = 0.f;
                if (col < NN) {
                    const float* vp = V + (size_t)col*384 + t*3;
                    v0 = vp[0]; v1 = vp[1]; v2 = vp[2];
                }
                float u0 = sunit[e*3+0], u1 = sunit[e*3+1], u2 = sunit[e*3+2];
                float* op = out + HN + (size_t)row*384 + t*3;
                atomicAdd(op + 0, v0*vg[e] + u0*rg);
                atomicAdd(op + 1, v1*vg[e] + u1*rg);
                atomicAdd(op + 2, v2*vg[e] + u2*rg);
            }
        }
    }
}

/* ---------- finalize: clip + mask ---------- */
__global__ void k_fin(float* __restrict__ out,
                      const unsigned char* __restrict__ m2d,
                      const unsigned char* __restrict__ m3d, int total)
{
    int idx = blockIdx.x*256 + threadIdx.x;
    if (idx >= total) return;
    int i = (idx < HN) ? (idx >> 7) : ((idx - HN) / 384);
    float v = out[idx];
    v = fminf(fmaxf(v, -100.f), 100.f);
    bool keep = ((m2d[i] | m3d[i] | g_mask[i]) != 0);
    out[idx] = keep ? v : 0.f;
}

#define SMEM_EDGE ((32*XSL + 64*129 + 2*32 + 4*32 + 96 + 32) * sizeof(float))

extern "C" void kernel_launch(void* const* d_in, const int* in_sizes, int n_in,
                              void* d_out, int out_size)
{
    int o = (in_sizes[3] == 1) ? 1 : 0;   /* layer_i scalar present? */
    const float* H      = (const float*)d_in[0];
    const float* V      = (const float*)d_in[1];
    const float* Z      = (const float*)d_in[2];
    const float* H2d    = (const float*)d_in[3+o];
    const unsigned char* m2d = (const unsigned char*)d_in[4+o];
    const int*   E2didx = (const int*)d_in[5+o];
    const float* E2dfeat= (const float*)d_in[6+o];
    const float* Z3d    = (const float*)d_in[7+o];
    const unsigned char* m3d = (const unsigned char*)d_in[8+o];
    const int*   Edidx  = (const int*)d_in[9+o];
    const float* Edval  = (const float*)d_in[10+o];
    const float* virt   = (const float*)d_in[11+o];
    const float* ETe    = (const float*)d_in[12+o];
    const float* Wrbf   = (const float*)d_in[13+o];
    const float* We2d   = (const float*)d_in[14+o];
    const float* Wi     = (const float*)d_in[15+o];
    const float* Wphi1  = (const float*)d_in[16+o];
    const float* bphi1  = (const float*)d_in[17+o];
    const float* Wphi2  = (const float*)d_in[18+o];
    const float* bphi2  = (const float*)d_in[19+o];
    const float* Wmsg   = (const float*)d_in[20+o];
    const float* bmsg   = (const float*)d_in[21+o];
    float* out = (float*)d_out;

    cudaMemsetAsync(d_out, 0, (size_t)out_size * sizeof(float));
    k_pre1<<<194, 256>>>(Wi, Wphi1, bphi1, We2d, Wrbf, ETe);
    k_pre2<<<1, 128>>>(Wi, Wphi1, virt);
    k_maskset<<<782, 256>>>(Edidx);
    k_nproj<<<1250, 128>>>(H, H2d);
    cudaFuncSetAttribute(k_edge, cudaFuncAttributeMaxDynamicSharedMemorySize,
                         (int)SMEM_EDGE);
    k_edge<<<NEF/32, 128, SMEM_EDGE>>>(E2didx, E2dfeat, Edidx, Edval, Z, Z3d, V,
                                       Wphi2, bphi2, Wmsg, bmsg, out);
    k_fin<<<(HN + 3*HN + 255)/256, 256>>>(out, m2d, m3d, HN + 3*HN);
}

// round 5
// speedup vs baseline: 1.1799x; 1.1799x over previous
#include <cuda_runtime.h>
#include <math.h>

#define NN   20000
#define E1C  100000
#define E2C  100000
#define HN   (NN*128)
#define CUTV 6.0f
#define PI_F 3.14159265358979f
#define XSL  192

#define NB0  3125          /* type-0 blocks (32 edges each) */
#define NB1  625           /* type-1 */
#define NB2  3125          /* type-2 */
#define NBT  (NB0+NB1+NB2) /* 6875   */

typedef unsigned long long u64t;

/* ---------------- persistent device scratch ---------------- */
__device__ __align__(16) float g_WcT[256*128];    /* (W1a@W_i)^T      [k][p] */
__device__ __align__(16) float g_Wc2dT[64*128];   /* (W1m@W_e2d)^T    [k][p] */
__device__ __align__(16) float g_WcrbfT[64*128];  /* (W1m@W_rbf)^T    [k][p] */
__device__ __align__(16) float g_etb[3*128];
__device__ __align__(16) float g_cvec[128];
__device__ __align__(16) float g_nproj[(size_t)2*NN*128];
__device__ __align__(16) float g_Wp2T[128*384];   /* W_phi2^T [k][q] */
__device__ __align__(16) float g_WmsgT[64*384];   /* W_msg^T  [k][q] */
__device__ unsigned char g_mask[NN];

/* -------- packed f32x2 helpers: .b64 regs via "l" constraint (not .f64!) -------- */
__device__ __forceinline__ u64t fma2d(u64t a, u64t b, u64t c) {
    u64t d; asm("fma.rn.f32x2 %0, %1, %2, %3;" : "=l"(d) : "l"(a), "l"(b), "l"(c));
    return d;
}
__device__ __forceinline__ u64t splat2(float x) {
    u64t d; asm("mov.b64 %0, {%1, %1};" : "=l"(d) : "r"(__float_as_uint(x)));
    return d;
}
__device__ __forceinline__ u64t fadd2(u64t a, u64t b) {
    return fma2d(a, splat2(1.0f), b);          /* rn(a*1+b) == rn(a+b) */
}
__device__ __forceinline__ u64t fmul2(u64t a, u64t b) {
    return fma2d(a, b, splat2(0.0f));          /* rn(a*b+0) == rn(a*b) */
}
__device__ __forceinline__ float lo2(u64t d) { return __uint_as_float((unsigned)(d & 0xffffffffull)); }
__device__ __forceinline__ float hi2(u64t d) { return __uint_as_float((unsigned)(d >> 32)); }
__device__ __forceinline__ void red2(float* p, float a, float b) {
    asm volatile("red.global.add.v2.f32 [%0], {%1, %2};" :: "l"(p), "f"(a), "f"(b) : "memory");
}

/* ---------------- precompute folded weights ---------------- */
__global__ void k_pre1(const float* __restrict__ W_i, const float* __restrict__ W_phi1,
                       const float* __restrict__ b_phi1, const float* __restrict__ W_e2d,
                       const float* __restrict__ W_rbf, const float* __restrict__ ET)
{
    int idx = blockIdx.x*256 + threadIdx.x;
    if (idx < NN) g_mask[idx] = 0;
    if (idx < 32768) {
        int k = idx >> 7, p = idx & 127;
        float s = 0.f;
        #pragma unroll 4
        for (int j = 0; j < 128; j++) s += W_phi1[p*288 + j] * W_i[j*256 + k];
        g_WcT[idx] = s;
    } else if (idx < 40960) {
        int i = idx - 32768; int k = i >> 7, p = i & 127;
        float s = 0.f;
        #pragma unroll 4
        for (int j = 0; j < 128; j++) s += W_phi1[p*288 + 128 + j] * W_e2d[j*64 + k];
        g_Wc2dT[i] = s;
    } else if (idx < 49152) {
        int i = idx - 40960; int k = i >> 7, p = i & 127;
        float s = 0.f;
        #pragma unroll 4
        for (int j = 0; j < 128; j++) s += W_phi1[p*288 + 128 + j] * W_rbf[j*64 + k];
        g_WcrbfT[i] = s;
    } else if (idx < 49536) {
        int i = idx - 49152; int tt = i >> 7, p = i & 127;
        float s = b_phi1[p];
        #pragma unroll
        for (int l = 0; l < 32; l++) s += W_phi1[p*288 + 256 + l] * ET[tt*32 + l];
        g_etb[i] = s;
    }
}

__global__ void k_pre2(const float* __restrict__ W_i, const float* __restrict__ W_phi1,
                       const float* __restrict__ virt)
{
    __shared__ float u[128];
    int t = threadIdx.x;
    float s = 0.f;
    #pragma unroll 4
    for (int j = 0; j < 128; j++) s += W_i[t*256 + 128 + j] * virt[j];
    u[t] = s;
    __syncthreads();
    float c = 0.f;
    #pragma unroll 4
    for (int q = 0; q < 128; q++) c += W_phi1[t*288 + q] * u[q];
    g_cvec[t] = c;
}

__global__ void k_pre3(const float* __restrict__ W_phi2, const float* __restrict__ W_msg)
{
    int idx = blockIdx.x*256 + threadIdx.x;
    if (idx < 128*384) {
        int k = idx / 384, q = idx % 384;
        g_Wp2T[idx] = W_phi2[(size_t)q*128 + k];
    } else {
        int j = idx - 128*384;
        if (j < 64*384) {
            int k = j / 384, q = j % 384;
            g_WmsgT[j] = W_msg[(size_t)q*64 + k];
        }
    }
}

__global__ void k_maskset(const int* __restrict__ Edist_idx)
{
    int idx = blockIdx.x*256 + threadIdx.x;
    if (idx < 2*E2C) g_mask[Edist_idx[idx]] = 1;
}

/* ---------------- node projection ---------------- */
__global__ void __launch_bounds__(128) k_nproj(const float* __restrict__ H,
                                               const float* __restrict__ H2d)
{
    __shared__ float hx[16*128];
    __shared__ float h2[16*128];
    int t = threadIdx.x;
    int i0 = blockIdx.x * 16;
    #pragma unroll
    for (int it = 0; it < 16; it++) {
        int idx = t + it*128;
        int nd = idx >> 7, p = idx & 127;
        hx[idx] = H  [(size_t)(i0+nd)*128 + p];
        h2[idx] = H2d[(size_t)(i0+nd)*128 + p];
    }
    __syncthreads();
    float a1[16], a2[16];
    #pragma unroll
    for (int nd = 0; nd < 16; nd++) { a1[nd] = 0.f; a2[nd] = 0.f; }
    for (int kk = 0; kk < 128; kk += 4) {
        float w0 = g_WcT[(kk+0)*128+t], w1 = g_WcT[(kk+1)*128+t];
        float w2 = g_WcT[(kk+2)*128+t], w3 = g_WcT[(kk+3)*128+t];
        float v0 = g_WcT[(128+kk+0)*128+t], v1 = g_WcT[(128+kk+1)*128+t];
        float v2 = g_WcT[(128+kk+2)*128+t], v3 = g_WcT[(128+kk+3)*128+t];
        #pragma unroll
        for (int nd = 0; nd < 16; nd++) {
            float4 f = *(const float4*)&hx[nd*128 + kk];
            a1[nd] += f.x*w0 + f.y*w1 + f.z*w2 + f.w*w3;
            float4 g = *(const float4*)&h2[nd*128 + kk];
            a2[nd] += g.x*v0 + g.y*v1 + g.z*v2 + g.w*v3;
        }
    }
    float cv = g_cvec[t];
    #pragma unroll
    for (int nd = 0; nd < 16; nd++) {
        g_nproj[(size_t)(i0+nd)*128 + t]    = a1[nd] + a2[nd];
        g_nproj[(size_t)(NN+i0+nd)*128 + t] = a1[nd] + cv;
    }
}

/* ---------------- packed GEMM micro-kernel: 8p x 4e, K=64 ---------------- */
__device__ __forceinline__ void gemm64(const float* __restrict__ wsp,
                                       const float* __restrict__ xsp,
                                       u64t (&acc)[4][4], int p0)
{
    for (int k4 = 0; k4 < 64; k4 += 4) {
        float4 xv[4];
        #pragma unroll
        for (int e = 0; e < 4; e++)
            xv[e] = *(const float4*)(xsp + e*XSL + k4);
        #pragma unroll
        for (int kk = 0; kk < 4; kk++) {
            ulonglong2 wA = *(const ulonglong2*)(wsp + (k4+kk)*128 + p0);
            ulonglong2 wB = *(const ulonglong2*)(wsp + (k4+kk)*128 + p0 + 4);
            #pragma unroll
            for (int e = 0; e < 4; e++) {
                float x = ((const float*)&xv[e])[kk];
                u64t a = splat2(x);
                acc[0][e] = fma2d(a, wA.x, acc[0][e]);
                acc[1][e] = fma2d(a, wA.y, acc[1][e]);
                acc[2][e] = fma2d(a, wB.x, acc[2][e]);
                acc[3][e] = fma2d(a, wB.y, acc[3][e]);
            }
        }
    }
}

/* ---------------- fused per-edge kernel: 32 edges / 128 threads ---------------- */
__global__ void __launch_bounds__(128, 3) k_edge(
    const int* __restrict__ E2d_idx, const float* __restrict__ E2d_feat,
    const int* __restrict__ Edist_idx, const float* __restrict__ Edist_val,
    const float* __restrict__ Z, const float* __restrict__ Z3d,
    const float* __restrict__ V,
    const float* __restrict__ b_phi2, const float* __restrict__ b_msg,
    float* __restrict__ out)
{
    extern __shared__ float sm[];
    float* smxs = sm;                       /* 32 x 192 */
    float* ws   = sm + 32*XSL;              /* 64 x 128 */
    int*   srow = (int*)(sm + 32*XSL + 64*128);
    int*   scol = srow + 32;
    float* sdist = (float*)(scol + 32);
    float* senvd = sdist + 32;
    float* sdval = senvd + 32;
    float* senv2 = sdval + 32;
    float* sunit = senv2 + 32;              /* 32 x 3 */

    int t  = threadIdx.x;
    int tp = t & 15;  int p0 = tp * 8;
    int te = t >> 4;  int e0 = te * 4;
    int bid = blockIdx.x;
    int base = bid * 32;
    int type = (bid < NB0) ? 0 : (bid < NB0+NB1 ? 1 : 2);

    /* --- metadata + geometry (warp 0) --- */
    if (t < 32) {
        int eg = base + t;
        int row, col; float dval = 0.f;
        if (type == 0)      { row = E2d_idx[eg]; col = E2d_idx[E1C + eg]; }
        else if (type == 1) { int i = eg - E1C; row = i; col = NN + i; }
        else                { int j = eg - E1C - NN; row = Edist_idx[j];
                              col = Edist_idx[E2C + j]; dval = Edist_val[j]; }
        srow[t] = row; scol[t] = col; sdval[t] = dval;
        float zr0 = Z[row*3+0], zr1 = Z[row*3+1], zr2 = Z[row*3+2];
        float zc0, zc1, zc2;
        if (col < NN) { zc0 = Z[col*3+0]; zc1 = Z[col*3+1]; zc2 = Z[col*3+2]; }
        else { int c2 = col - NN; zc0 = Z3d[c2*3+0]; zc1 = Z3d[c2*3+1]; zc2 = Z3d[c2*3+2]; }
        float r0 = zr0-zc0, r1 = zr1-zc1, r2 = zr2-zc2;
        float d = sqrtf(r0*r0 + r1*r1 + r2*r2 + 1e-8f);
        sdist[t] = d;
        float inv = 1.0f / d;
        sunit[t*3+0] = r0*inv; sunit[t*3+1] = r1*inv; sunit[t*3+2] = r2*inv;
        float cl = fminf(d * (1.0f/CUTV), 1.0f);
        senvd[t] = 0.5f * (cosf(PI_F*cl) + 1.0f);
        float cl2 = fminf(fmaxf(dval * (1.0f/CUTV), 0.f), 1.0f);
        senv2[t] = 0.5f * (cosf(PI_F*cl2) + 1.0f);
    }
    /* --- phase-A weights into shared (types 0/2) --- */
    if (type == 0) {
        #pragma unroll
        for (int i = t; i < 2048; i += 128)
            ((float4*)ws)[i] = ((const float4*)g_Wc2dT)[i];
    } else if (type == 2) {
        #pragma unroll
        for (int i = t; i < 2048; i += 128)
            ((float4*)ws)[i] = ((const float4*)g_WcrbfT)[i];
    }
    __syncthreads();

    /* --- per-edge 64-dim features into xs[e][128..191] --- */
    const float cstep = CUTV / 63.0f;
    const float i2w2  = 1.0f / (2.0f * (CUTV/64.0f) * (CUTV/64.0f));
    if (type == 0) {
        #pragma unroll
        for (int it = 0; it < 16; it++) {
            int idx = t + it*128; int e = idx & 31, k = idx >> 5;
            smxs[e*XSL + 128 + k] = E2d_feat[(size_t)k*E1C + base + e];
        }
    } else if (type == 2) {
        #pragma unroll
        for (int it = 0; it < 16; it++) {
            int idx = t + it*128; int e = idx & 31, k = idx >> 5;
            float diff = sdval[e] - k*cstep;
            smxs[e*XSL + 128 + k] = expf(-diff*diff*i2w2) * senv2[e];
        }
    }
    /* --- gather node projection while feats land --- */
    u64t gn[4][4];
    #pragma unroll
    for (int e = 0; e < 4; e++) {
        const float* np = g_nproj + (size_t)scol[e0+e]*128 + p0;
        ulonglong2 ga = *(const ulonglong2*)np;
        ulonglong2 gb = *(const ulonglong2*)(np + 4);
        gn[e][0] = ga.x; gn[e][1] = ga.y; gn[e][2] = gb.x; gn[e][3] = gb.y;
    }
    u64t et2[4];
    {
        ulonglong2 ea = *(const ulonglong2*)(g_etb + type*128 + p0);
        ulonglong2 eb = *(const ulonglong2*)(g_etb + type*128 + p0 + 4);
        et2[0] = ea.x; et2[1] = ea.y; et2[2] = eb.x; et2[3] = eb.y;
    }
    __syncthreads();

    /* --- phase A: act = nproj[col] + etb (+ feats @ Wtype^T) ; silu --- */
    {
        u64t acc[4][4] = {};
        if (type != 1) gemm64(ws, smxs + e0*XSL + 128, acc, p0);
        #pragma unroll
        for (int e = 0; e < 4; e++) {
            #pragma unroll
            for (int pp = 0; pp < 4; pp++) {
                u64t s = fadd2(acc[pp][e], fadd2(gn[e][pp], et2[pp]));
                float a = lo2(s), b = hi2(s);
                a = a / (1.0f + expf(-a));
                b = b / (1.0f + expf(-b));
                *(float2*)&smxs[(e0+e)*XSL + p0 + 2*pp] = make_float2(a, b);
            }
        }
    }
    __syncthreads();

    /* --- geometric RBF overwrites feats --- */
    #pragma unroll
    for (int it = 0; it < 16; it++) {
        int idx = t + it*128; int e = idx & 31, k = idx >> 5;
        float diff = sdist[e] - k*cstep;
        smxs[e*XSL + 128 + k] = expf(-diff*diff*i2w2) * senvd[e];
    }

    /* --- phase C: [phi | wd] + fused scatter --- */
    u64t vg2[4][4];
    for (int qc = 0; qc < 3; qc++) {
        u64t accp[4][4] = {};
        #pragma unroll 1
        for (int kc = 0; kc < 2; kc++) {
            __syncthreads();
            {
                const float* src = g_Wp2T + (size_t)(kc*64)*384 + qc*128;
                #pragma unroll
                for (int i = t; i < 2048; i += 128) {
                    int k = i >> 5, j = i & 31;
                    *(float4*)(ws + k*128 + j*4) = *(const float4*)(src + (size_t)k*384 + j*4);
                }
            }
            __syncthreads();
            gemm64(ws, smxs + e0*XSL + kc*64, accp, p0);
        }
        u64t accw[4][4] = {};
        __syncthreads();
        {
            const float* src = g_WmsgT + qc*128;
            #pragma unroll
            for (int i = t; i < 2048; i += 128) {
                int k = i >> 5, j = i & 31;
                *(float4*)(ws + k*128 + j*4) = *(const float4*)(src + (size_t)k*384 + j*4);
            }
        }
        __syncthreads();
        gemm64(ws, smxs + e0*XSL + 128, accw, p0);

        u64t bpp[4], bmm[4];
        {
            ulonglong2 a = *(const ulonglong2*)(b_phi2 + qc*128 + p0);
            ulonglong2 b = *(const ulonglong2*)(b_phi2 + qc*128 + p0 + 4);
            bpp[0] = a.x; bpp[1] = a.y; bpp[2] = b.x; bpp[3] = b.y;
            ulonglong2 c = *(const ulonglong2*)(b_msg + qc*128 + p0);
            ulonglong2 d = *(const ulonglong2*)(b_msg + qc*128 + p0 + 4);
            bmm[0] = c.x; bmm[1] = c.y; bmm[2] = d.x; bmm[3] = d.y;
        }
        u64t m2[4][4];
        #pragma unroll
        for (int pp = 0; pp < 4; pp++)
            #pragma unroll
            for (int e = 0; e < 4; e++)
                m2[pp][e] = fmul2(fadd2(accp[pp][e], bpp[pp]),
                                  fadd2(accw[pp][e], bmm[pp]));

        if (qc == 0) {
            #pragma unroll
            for (int e = 0; e < 4; e++) {
                float* hp = out + (size_t)srow[e0+e]*128 + p0;
                #pragma unroll
                for (int pp = 0; pp < 4; pp++)
                    red2(hp + 2*pp, lo2(m2[pp][e]), hi2(m2[pp][e]));
            }
        } else if (qc == 1) {
            #pragma unroll
            for (int pp = 0; pp < 4; pp++)
                #pragma unroll
                for (int e = 0; e < 4; e++)
                    vg2[pp][e] = m2[pp][e];
        } else {
            #pragma unroll
            for (int e = 0; e < 4; e++) {
                int eg2 = e0 + e;
                int row = srow[eg2], col = scol[eg2];
                float u0 = sunit[eg2*3+0], u1 = sunit[eg2*3+1], u2 = sunit[eg2*3+2];
                float vb[24];
                if (type != 1) {
                    const float4* vp = (const float4*)(V + (size_t)col*384 + p0*3);
                    #pragma unroll
                    for (int q = 0; q < 6; q++) ((float4*)vb)[q] = vp[q];
                } else {
                    #pragma unroll
                    for (int q = 0; q < 24; q++) vb[q] = 0.f;
                }
                float* op = out + HN + (size_t)row*384 + p0*3;
                #pragma unroll
                for (int pp = 0; pp < 4; pp++) {
                    float vgl = lo2(vg2[pp][e]), vgh = hi2(vg2[pp][e]);
                    float rgl = lo2(m2[pp][e]),  rgh = hi2(m2[pp][e]);
                    int b = pp*6;
                    float d0 = vb[b+0]*vgl + u0*rgl;
                    float d1 = vb[b+1]*vgl + u1*rgl;
                    float d2 = vb[b+2]*vgl + u2*rgl;
                    float d3 = vb[b+3]*vgh + u0*rgh;
                    float d4 = vb[b+4]*vgh + u1*rgh;
                    float d5 = vb[b+5]*vgh + u2*rgh;
                    red2(op + b + 0, d0, d1);
                    red2(op + b + 2, d2, d3);
                    red2(op + b + 4, d4, d5);
                }
            }
        }
    }
}

/* ---------------- finalize ---------------- */
__global__ void k_fin(float* __restrict__ out,
                      const unsigned char* __restrict__ m2d,
                      const unsigned char* __restrict__ m3d, int total)
{
    int idx = blockIdx.x*256 + threadIdx.x;
    if (idx >= total) return;
    int i = (idx < HN) ? (idx >> 7) : ((idx - HN) / 384);
    float v = out[idx];
    v = fminf(fmaxf(v, -100.f), 100.f);
    bool keep = ((m2d[i] | m3d[i] | g_mask[i]) != 0);
    out[idx] = keep ? v : 0.f;
}

#define SMEM_EDGE ((32*XSL + 64*128 + 2*32 + 4*32 + 96 + 32) * sizeof(float))

extern "C" void kernel_launch(void* const* d_in, const int* in_sizes, int n_in,
                              void* d_out, int out_size)
{
    int o = (in_sizes[3] == 1) ? 1 : 0;
    const float* H      = (const float*)d_in[0];
    const float* V      = (const float*)d_in[1];
    const float* Z      = (const float*)d_in[2];
    const float* H2d    = (const float*)d_in[3+o];
    const unsigned char* m2d = (const unsigned char*)d_in[4+o];
    const int*   E2didx = (const int*)d_in[5+o];
    const float* E2dfeat= (const float*)d_in[6+o];
    const float* Z3d    = (const float*)d_in[7+o];
    const unsigned char* m3d = (const unsigned char*)d_in[8+o];
    const int*   Edidx  = (const int*)d_in[9+o];
    const float* Edval  = (const float*)d_in[10+o];
    const float* virt   = (const float*)d_in[11+o];
    const float* ETe    = (const float*)d_in[12+o];
    const float* Wrbf   = (const float*)d_in[13+o];
    const float* We2d   = (const float*)d_in[14+o];
    const float* Wi     = (const float*)d_in[15+o];
    const float* Wphi1  = (const float*)d_in[16+o];
    const float* bphi1  = (const float*)d_in[17+o];
    const float* Wphi2  = (const float*)d_in[18+o];
    const float* bphi2  = (const float*)d_in[19+o];
    const float* Wmsg   = (const float*)d_in[20+o];
    const float* bmsg   = (const float*)d_in[21+o];
    float* out = (float*)d_out;

    cudaMemsetAsync(d_out, 0, (size_t)out_size * sizeof(float));
    k_pre1<<<194, 256>>>(Wi, Wphi1, bphi1, We2d, Wrbf, ETe);
    k_pre2<<<1, 128>>>(Wi, Wphi1, virt);
    k_pre3<<<288, 256>>>(Wphi2, Wmsg);
    k_maskset<<<782, 256>>>(Edidx);
    k_nproj<<<1250, 128>>>(H, H2d);
    cudaFuncSetAttribute(k_edge, cudaFuncAttributeMaxDynamicSharedMemorySize,
                         (int)SMEM_EDGE);
    k_edge<<<NBT, 128, SMEM_EDGE>>>(E2didx, E2dfeat, Edidx, Edval, Z, Z3d, V,
                                    bphi2, bmsg, out);
    k_fin<<<(HN + 3*HN + 255)/256, 256>>>(out, m2d, m3d, HN + 3*HN);
}

// round 6
// speedup vs baseline: 1.2685x; 1.0751x over previous
#include <cuda_runtime.h>
#include <math.h>

#define NN   20000
#define E1C  100000
#define E2C  100000
#define HN   (NN*128)
#define CUTV 6.0f
#define PI_F 3.14159265358979f
#define XSL  192

#define NB0  3125          /* type-0 blocks (32 edges each) */
#define NB1  625           /* type-1 */
#define NB2  3125          /* type-2 */
#define NBT  (NB0+NB1+NB2) /* 6875   */

typedef unsigned long long u64t;

/* ---------------- persistent device scratch ---------------- */
__device__ __align__(16) float g_WcT[256*128];    /* (W1a@W_i)^T      [k][p] */
__device__ __align__(16) float g_Wc2dT[64*128];   /* (W1m@W_e2d)^T    [k][p] */
__device__ __align__(16) float g_WcrbfT[64*128];  /* (W1m@W_rbf)^T    [k][p] */
__device__ __align__(16) float g_etb[3*128];
__device__ __align__(16) float g_cvec[128];
__device__ __align__(16) float g_nproj[(size_t)2*NN*128];
__device__ __align__(16) float g_Wp2T[128*384];   /* W_phi2^T [k][q] */
__device__ __align__(16) float g_WmsgT[64*384];   /* W_msg^T  [k][q] */
__device__ unsigned char g_mask[NN];

/* -------- packed f32x2 helpers (.b64 regs via "l") -------- */
__device__ __forceinline__ u64t fma2d(u64t a, u64t b, u64t c) {
    u64t d; asm("fma.rn.f32x2 %0, %1, %2, %3;" : "=l"(d) : "l"(a), "l"(b), "l"(c));
    return d;
}
__device__ __forceinline__ u64t splat2(float x) {
    u64t d; asm("mov.b64 %0, {%1, %1};" : "=l"(d) : "r"(__float_as_uint(x)));
    return d;
}
__device__ __forceinline__ u64t fadd2(u64t a, u64t b) { return fma2d(a, splat2(1.0f), b); }
__device__ __forceinline__ u64t fmul2(u64t a, u64t b) { return fma2d(a, b, splat2(0.0f)); }
__device__ __forceinline__ float lo2(u64t d) { return __uint_as_float((unsigned)(d & 0xffffffffull)); }
__device__ __forceinline__ float hi2(u64t d) { return __uint_as_float((unsigned)(d >> 32)); }
__device__ __forceinline__ void red4(float* p, float a, float b, float c, float d) {
    asm volatile("red.global.add.v4.f32 [%0], {%1, %2, %3, %4};"
                 :: "l"(p), "f"(a), "f"(b), "f"(c), "f"(d) : "memory");
}
/* -------- cp.async helpers -------- */
__device__ __forceinline__ void cp16(void* smem_dst, const void* gmem_src) {
    unsigned s = (unsigned)__cvta_generic_to_shared(smem_dst);
    asm volatile("cp.async.ca.shared.global [%0], [%1], 16;" :: "r"(s), "l"(gmem_src));
}
__device__ __forceinline__ void cp_commit_wait() {
    asm volatile("cp.async.commit_group;" ::: "memory");
    asm volatile("cp.async.wait_group 0;" ::: "memory");
}

/* ---------------- fused precompute (one kernel: launch-slot control) ---------------- */
__global__ void k_pre(const float* __restrict__ W_i, const float* __restrict__ W_phi1,
                      const float* __restrict__ b_phi1, const float* __restrict__ W_e2d,
                      const float* __restrict__ W_rbf, const float* __restrict__ ET,
                      const float* __restrict__ virt,
                      const float* __restrict__ W_phi2, const float* __restrict__ W_msg)
{
    int b = blockIdx.x;
    int t = threadIdx.x;
    if (b < 194) {
        int idx = b*256 + t;
        if (idx < NN) g_mask[idx] = 0;
        if (idx < 32768) {
            int k = idx >> 7, p = idx & 127;
            float s = 0.f;
            #pragma unroll 4
            for (int j = 0; j < 128; j++) s += W_phi1[p*288 + j] * W_i[j*256 + k];
            g_WcT[idx] = s;
        } else if (idx < 40960) {
            int i = idx - 32768; int k = i >> 7, p = i & 127;
            float s = 0.f;
            #pragma unroll 4
            for (int j = 0; j < 128; j++) s += W_phi1[p*288 + 128 + j] * W_e2d[j*64 + k];
            g_Wc2dT[i] = s;
        } else if (idx < 49152) {
            int i = idx - 40960; int k = i >> 7, p = i & 127;
            float s = 0.f;
            #pragma unroll 4
            for (int j = 0; j < 128; j++) s += W_phi1[p*288 + 128 + j] * W_rbf[j*64 + k];
            g_WcrbfT[i] = s;
        } else if (idx < 49536) {
            int i = idx - 49152; int tt = i >> 7, p = i & 127;
            float s = b_phi1[p];
            #pragma unroll
            for (int l = 0; l < 32; l++) s += W_phi1[p*288 + 256 + l] * ET[tt*32 + l];
            g_etb[i] = s;
        }
    } else if (b == 194) {
        __shared__ float u[128];
        if (t < 128) {
            float s = 0.f;
            #pragma unroll 4
            for (int j = 0; j < 128; j++) s += W_i[t*256 + 128 + j] * virt[j];
            u[t] = s;
        }
        __syncthreads();
        if (t < 128) {
            float c = 0.f;
            #pragma unroll 4
            for (int q = 0; q < 128; q++) c += W_phi1[t*288 + q] * u[q];
            g_cvec[t] = c;
        }
    } else {
        int idx = (b - 195)*256 + t;
        if (idx < 128*384) {
            int k = idx / 384, q = idx % 384;
            g_Wp2T[idx] = W_phi2[(size_t)q*128 + k];
        } else {
            int j = idx - 128*384;
            if (j < 64*384) {
                int k = j / 384, q = j % 384;
                g_WmsgT[j] = W_msg[(size_t)q*64 + k];
            }
        }
    }
}

__global__ void k_maskset(const int* __restrict__ Edist_idx)
{
    int idx = blockIdx.x*256 + threadIdx.x;
    if (idx < 2*E2C) g_mask[Edist_idx[idx]] = 1;
}

/* ---------------- node projection ---------------- */
__global__ void __launch_bounds__(128) k_nproj(const float* __restrict__ H,
                                               const float* __restrict__ H2d)
{
    __shared__ float hx[16*128];
    __shared__ float h2[16*128];
    int t = threadIdx.x;
    int i0 = blockIdx.x * 16;
    #pragma unroll
    for (int it = 0; it < 16; it++) {
        int idx = t + it*128;
        int nd = idx >> 7, p = idx & 127;
        hx[idx] = H  [(size_t)(i0+nd)*128 + p];
        h2[idx] = H2d[(size_t)(i0+nd)*128 + p];
    }
    __syncthreads();
    float a1[16], a2[16];
    #pragma unroll
    for (int nd = 0; nd < 16; nd++) { a1[nd] = 0.f; a2[nd] = 0.f; }
    for (int kk = 0; kk < 128; kk += 4) {
        float w0 = g_WcT[(kk+0)*128+t], w1 = g_WcT[(kk+1)*128+t];
        float w2 = g_WcT[(kk+2)*128+t], w3 = g_WcT[(kk+3)*128+t];
        float v0 = g_WcT[(128+kk+0)*128+t], v1 = g_WcT[(128+kk+1)*128+t];
        float v2 = g_WcT[(128+kk+2)*128+t], v3 = g_WcT[(128+kk+3)*128+t];
        #pragma unroll
        for (int nd = 0; nd < 16; nd++) {
            float4 f = *(const float4*)&hx[nd*128 + kk];
            a1[nd] += f.x*w0 + f.y*w1 + f.z*w2 + f.w*w3;
            float4 g = *(const float4*)&h2[nd*128 + kk];
            a2[nd] += g.x*v0 + g.y*v1 + g.z*v2 + g.w*v3;
        }
    }
    float cv = g_cvec[t];
    #pragma unroll
    for (int nd = 0; nd < 16; nd++) {
        g_nproj[(size_t)(i0+nd)*128 + t]    = a1[nd] + a2[nd];
        g_nproj[(size_t)(NN+i0+nd)*128 + t] = a1[nd] + cv;
    }
}

/* ---------------- packed GEMM micro-kernel: 8p x 4e, K=64 ---------------- */
__device__ __forceinline__ void gemm64(const float* __restrict__ wsp,
                                       const float* __restrict__ xsp,
                                       u64t (&acc)[4][4], int p0)
{
    for (int k4 = 0; k4 < 64; k4 += 4) {
        float4 xv[4];
        #pragma unroll
        for (int e = 0; e < 4; e++)
            xv[e] = *(const float4*)(xsp + e*XSL + k4);
        #pragma unroll
        for (int kk = 0; kk < 4; kk++) {
            ulonglong2 wA = *(const ulonglong2*)(wsp + (k4+kk)*128 + p0);
            ulonglong2 wB = *(const ulonglong2*)(wsp + (k4+kk)*128 + p0 + 4);
            #pragma unroll
            for (int e = 0; e < 4; e++) {
                float x = ((const float*)&xv[e])[kk];
                u64t a = splat2(x);
                acc[0][e] = fma2d(a, wA.x, acc[0][e]);
                acc[1][e] = fma2d(a, wA.y, acc[1][e]);
                acc[2][e] = fma2d(a, wB.x, acc[2][e]);
                acc[3][e] = fma2d(a, wB.y, acc[3][e]);
            }
        }
    }
}

/* ---------------- fused per-edge kernel: 32 edges / 128 threads ---------------- */
__global__ void __launch_bounds__(128, 3) k_edge(
    const int* __restrict__ E2d_idx, const float* __restrict__ E2d_feat,
    const int* __restrict__ Edist_idx, const float* __restrict__ Edist_val,
    const float* __restrict__ Z, const float* __restrict__ Z3d,
    const float* __restrict__ V,
    const float* __restrict__ b_phi2, const float* __restrict__ b_msg,
    float* __restrict__ out)
{
    extern __shared__ float sm[];
    float* smxs = sm;                       /* 32 x 192 */
    float* ws   = sm + 32*XSL;              /* 64 x 128 */
    int*   srow = (int*)(sm + 32*XSL + 64*128);
    int*   scol = srow + 32;
    float* sdist = (float*)(scol + 32);
    float* senvd = sdist + 32;
    float* sdval = senvd + 32;
    float* senv2 = sdval + 32;
    float* sunit = senv2 + 32;              /* 32 x 3 */

    int t  = threadIdx.x;
    int tp = t & 15;  int p0 = tp * 8;
    int te = t >> 4;  int e0 = te * 4;
    int bid = blockIdx.x;
    int base = bid * 32;
    int type = (bid < NB0) ? 0 : (bid < NB0+NB1 ? 1 : 2);

    /* --- phase-A weights via cp.async (types 0/2) --- */
    if (type == 0) {
        const float4* src = (const float4*)g_Wc2dT;
        #pragma unroll
        for (int i = t; i < 2048; i += 128) cp16(&((float4*)ws)[i], &src[i]);
    } else if (type == 2) {
        const float4* src = (const float4*)g_WcrbfT;
        #pragma unroll
        for (int i = t; i < 2048; i += 128) cp16(&((float4*)ws)[i], &src[i]);
    }

    /* --- metadata + geometry (warp 0) --- */
    if (t < 32) {
        int eg = base + t;
        int row, col; float dval = 0.f;
        if (type == 0)      { row = E2d_idx[eg]; col = E2d_idx[E1C + eg]; }
        else if (type == 1) { int i = eg - E1C; row = i; col = NN + i; }
        else                { int j = eg - E1C - NN; row = Edist_idx[j];
                              col = Edist_idx[E2C + j]; dval = Edist_val[j]; }
        srow[t] = row; scol[t] = col; sdval[t] = dval;
        float zr0 = Z[row*3+0], zr1 = Z[row*3+1], zr2 = Z[row*3+2];
        float zc0, zc1, zc2;
        if (col < NN) { zc0 = Z[col*3+0]; zc1 = Z[col*3+1]; zc2 = Z[col*3+2]; }
        else { int c2 = col - NN; zc0 = Z3d[c2*3+0]; zc1 = Z3d[c2*3+1]; zc2 = Z3d[c2*3+2]; }
        float r0 = zr0-zc0, r1 = zr1-zc1, r2 = zr2-zc2;
        float d = sqrtf(r0*r0 + r1*r1 + r2*r2 + 1e-8f);
        sdist[t] = d;
        float inv = 1.0f / d;
        sunit[t*3+0] = r0*inv; sunit[t*3+1] = r1*inv; sunit[t*3+2] = r2*inv;
        float cl = fminf(d * (1.0f/CUTV), 1.0f);
        senvd[t] = 0.5f * (cosf(PI_F*cl) + 1.0f);
        float cl2 = fminf(fmaxf(dval * (1.0f/CUTV), 0.f), 1.0f);
        senv2[t] = 0.5f * (cosf(PI_F*cl2) + 1.0f);
    }
    cp_commit_wait();
    __syncthreads();

    /* --- per-edge 64-dim features into xs[e][128..191] --- */
    const float cstep = CUTV / 63.0f;
    const float i2w2  = 1.0f / (2.0f * (CUTV/64.0f) * (CUTV/64.0f));
    if (type == 0) {
        #pragma unroll
        for (int it = 0; it < 16; it++) {
            int idx = t + it*128; int e = idx & 31, k = idx >> 5;
            smxs[e*XSL + 128 + k] = E2d_feat[(size_t)k*E1C + base + e];
        }
    } else if (type == 2) {
        #pragma unroll
        for (int it = 0; it < 16; it++) {
            int idx = t + it*128; int e = idx & 31, k = idx >> 5;
            float diff = sdval[e] - k*cstep;
            smxs[e*XSL + 128 + k] = expf(-diff*diff*i2w2) * senv2[e];
        }
    }
    /* --- gather node projection --- */
    u64t gn[4][4];
    #pragma unroll
    for (int e = 0; e < 4; e++) {
        const float* np = g_nproj + (size_t)scol[e0+e]*128 + p0;
        ulonglong2 ga = *(const ulonglong2*)np;
        ulonglong2 gb = *(const ulonglong2*)(np + 4);
        gn[e][0] = ga.x; gn[e][1] = ga.y; gn[e][2] = gb.x; gn[e][3] = gb.y;
    }
    u64t et2[4];
    {
        ulonglong2 ea = *(const ulonglong2*)(g_etb + type*128 + p0);
        ulonglong2 eb = *(const ulonglong2*)(g_etb + type*128 + p0 + 4);
        et2[0] = ea.x; et2[1] = ea.y; et2[2] = eb.x; et2[3] = eb.y;
    }
    __syncthreads();

    /* --- phase A: act = nproj[col] + etb (+ feats @ Wtype^T) ; silu --- */
    {
        u64t acc[4][4] = {};
        if (type != 1) gemm64(ws, smxs + e0*XSL + 128, acc, p0);
        #pragma unroll
        for (int e = 0; e < 4; e++) {
            #pragma unroll
            for (int pp = 0; pp < 4; pp++) {
                u64t s = fadd2(acc[pp][e], fadd2(gn[e][pp], et2[pp]));
                float a = lo2(s), b = hi2(s);
                a = a / (1.0f + expf(-a));
                b = b / (1.0f + expf(-b));
                *(float2*)&smxs[(e0+e)*XSL + p0 + 2*pp] = make_float2(a, b);
            }
        }
    }
    __syncthreads();

    /* --- geometric RBF overwrites feats --- */
    #pragma unroll
    for (int it = 0; it < 16; it++) {
        int idx = t + it*128; int e = idx & 31, k = idx >> 5;
        float diff = sdist[e] - k*cstep;
        smxs[e*XSL + 128 + k] = expf(-diff*diff*i2w2) * senvd[e];
    }

    /* --- phase C, qc order {1,2,0}: vg first, V scatter, then H scatter --- */
    u64t vg2[4][4];
    #pragma unroll 1
    for (int qi = 0; qi < 3; qi++) {
        int qc = (qi == 0) ? 1 : (qi == 1 ? 2 : 0);
        u64t accp[4][4] = {};
        #pragma unroll 1
        for (int kc = 0; kc < 2; kc++) {
            __syncthreads();
            {
                const float* src = g_Wp2T + (size_t)(kc*64)*384 + qc*128;
                #pragma unroll
                for (int i = t; i < 2048; i += 128) {
                    int k = i >> 5, j = i & 31;
                    cp16(ws + k*128 + j*4, src + (size_t)k*384 + j*4);
                }
            }
            cp_commit_wait();
            __syncthreads();
            gemm64(ws, smxs + e0*XSL + kc*64, accp, p0);
        }
        u64t accw[4][4] = {};
        __syncthreads();
        {
            const float* src = g_WmsgT + qc*128;
            #pragma unroll
            for (int i = t; i < 2048; i += 128) {
                int k = i >> 5, j = i & 31;
                cp16(ws + k*128 + j*4, src + (size_t)k*384 + j*4);
            }
        }
        cp_commit_wait();
        __syncthreads();
        gemm64(ws, smxs + e0*XSL + 128, accw, p0);

        u64t bpp[4], bmm[4];
        {
            ulonglong2 a = *(const ulonglong2*)(b_phi2 + qc*128 + p0);
            ulonglong2 b = *(const ulonglong2*)(b_phi2 + qc*128 + p0 + 4);
            bpp[0] = a.x; bpp[1] = a.y; bpp[2] = b.x; bpp[3] = b.y;
            ulonglong2 c = *(const ulonglong2*)(b_msg + qc*128 + p0);
            ulonglong2 d = *(const ulonglong2*)(b_msg + qc*128 + p0 + 4);
            bmm[0] = c.x; bmm[1] = c.y; bmm[2] = d.x; bmm[3] = d.y;
        }
        u64t m2[4][4];
        #pragma unroll
        for (int pp = 0; pp < 4; pp++)
            #pragma unroll
            for (int e = 0; e < 4; e++)
                m2[pp][e] = fmul2(fadd2(accp[pp][e], bpp[pp]),
                                  fadd2(accw[pp][e], bmm[pp]));

        if (qc == 1) {
            #pragma unroll
            for (int pp = 0; pp < 4; pp++)
                #pragma unroll
                for (int e = 0; e < 4; e++)
                    vg2[pp][e] = m2[pp][e];
        } else if (qc == 2) {
            #pragma unroll
            for (int e = 0; e < 4; e++) {
                int eg2 = e0 + e;
                int row = srow[eg2], col = scol[eg2];
                float u0 = sunit[eg2*3+0], u1 = sunit[eg2*3+1], u2 = sunit[eg2*3+2];
                float vb[24];
                if (type != 1) {
                    const float4* vp = (const float4*)(V + (size_t)col*384 + p0*3);
                    #pragma unroll
                    for (int q = 0; q < 6; q++) ((float4*)vb)[q] = vp[q];
                } else {
                    #pragma unroll
                    for (int q = 0; q < 24; q++) vb[q] = 0.f;
                }
                float dv[24];
                #pragma unroll
                for (int pp = 0; pp < 4; pp++) {
                    float vgl = lo2(vg2[pp][e]), vgh = hi2(vg2[pp][e]);
                    float rgl = lo2(m2[pp][e]),  rgh = hi2(m2[pp][e]);
                    int b = pp*6;
                    dv[b+0] = vb[b+0]*vgl + u0*rgl;
                    dv[b+1] = vb[b+1]*vgl + u1*rgl;
                    dv[b+2] = vb[b+2]*vgl + u2*rgl;
                    dv[b+3] = vb[b+3]*vgh + u0*rgh;
                    dv[b+4] = vb[b+4]*vgh + u1*rgh;
                    dv[b+5] = vb[b+5]*vgh + u2*rgh;
                }
                float* op = out + HN + (size_t)row*384 + p0*3;
                #pragma unroll
                for (int q = 0; q < 6; q++)
                    red4(op + q*4, dv[q*4+0], dv[q*4+1], dv[q*4+2], dv[q*4+3]);
            }
        } else { /* qc == 0 : H scatter */
            #pragma unroll
            for (int e = 0; e < 4; e++) {
                float* hp = out + (size_t)srow[e0+e]*128 + p0;
                red4(hp,     lo2(m2[0][e]), hi2(m2[0][e]), lo2(m2[1][e]), hi2(m2[1][e]));
                red4(hp + 4, lo2(m2[2][e]), hi2(m2[2][e]), lo2(m2[3][e]), hi2(m2[3][e]));
            }
        }
    }
}

/* ---------------- finalize ---------------- */
__global__ void k_fin(float* __restrict__ out,
                      const unsigned char* __restrict__ m2d,
                      const unsigned char* __restrict__ m3d, int total)
{
    int idx = blockIdx.x*256 + threadIdx.x;
    if (idx >= total) return;
    int i = (idx < HN) ? (idx >> 7) : ((idx - HN) / 384);
    float v = out[idx];
    v = fminf(fmaxf(v, -100.f), 100.f);
    bool keep = ((m2d[i] | m3d[i] | g_mask[i]) != 0);
    out[idx] = keep ? v : 0.f;
}

#define SMEM_EDGE ((32*XSL + 64*128 + 2*32 + 4*32 + 96 + 32) * sizeof(float))

extern "C" void kernel_launch(void* const* d_in, const int* in_sizes, int n_in,
                              void* d_out, int out_size)
{
    int o = (in_sizes[3] == 1) ? 1 : 0;
    const float* H      = (const float*)d_in[0];
    const float* V      = (const float*)d_in[1];
    const float* Z      = (const float*)d_in[2];
    const float* H2d    = (const float*)d_in[3+o];
    const unsigned char* m2d = (const unsigned char*)d_in[4+o];
    const int*   E2didx = (const int*)d_in[5+o];
    const float* E2dfeat= (const float*)d_in[6+o];
    const float* Z3d    = (const float*)d_in[7+o];
    const unsigned char* m3d = (const unsigned char*)d_in[8+o];
    const int*   Edidx  = (const int*)d_in[9+o];
    const float* Edval  = (const float*)d_in[10+o];
    const float* virt   = (const float*)d_in[11+o];
    const float* ETe    = (const float*)d_in[12+o];
    const float* Wrbf   = (const float*)d_in[13+o];
    const float* We2d   = (const float*)d_in[14+o];
    const float* Wi     = (const float*)d_in[15+o];
    const float* Wphi1  = (const float*)d_in[16+o];
    const float* bphi1  = (const float*)d_in[17+o];
    const float* Wphi2  = (const float*)d_in[18+o];
    const float* bphi2  = (const float*)d_in[19+o];
    const float* Wmsg   = (const float*)d_in[20+o];
    const float* bmsg   = (const float*)d_in[21+o];
    float* out = (float*)d_out;

    cudaMemsetAsync(d_out, 0, (size_t)out_size * sizeof(float));
    k_pre<<<483, 256>>>(Wi, Wphi1, bphi1, We2d, Wrbf, ETe, virt, Wphi2, Wmsg);
    k_maskset<<<782, 256>>>(Edidx);
    k_nproj<<<1250, 128>>>(H, H2d);
    cudaFuncSetAttribute(k_edge, cudaFuncAttributeMaxDynamicSharedMemorySize,
                         (int)SMEM_EDGE);
    k_edge<<<NBT, 128, SMEM_EDGE>>>(E2didx, E2dfeat, Edidx, Edval, Z, Z3d, V,
                                    bphi2, bmsg, out);
    k_fin<<<(HN + 3*HN + 255)/256, 256>>>(out, m2d, m3d, HN + 3*HN);
}

// round 7
// speedup vs baseline: 1.8237x; 1.4377x over previous
#include <cuda_runtime.h>
#include <math.h>

#define NN   20000
#define E1C  100000
#define E2C  100000
#define HN   (NN*128)
#define CUTV 6.0f
#define PI_F 3.14159265358979f
#define XSL  196   /* 32x196 floats; 196%32=4 banks -> conflict-free te access */

#define NB0  3125
#define NB1  625
#define NB2  3125
#define NBT  (NB0+NB1+NB2)

typedef unsigned long long u64t;

/* ---------------- persistent device scratch ---------------- */
__device__ __align__(16) float g_WcT[256*128];
__device__ __align__(16) float g_Wc2dT[64*128];
__device__ __align__(16) float g_WcrbfT[64*128];
__device__ __align__(16) float g_etb[3*128];
__device__ __align__(16) float g_cvec[128];
__device__ __align__(16) float g_nproj[(size_t)2*NN*128];
__device__ __align__(16) float g_Wp2T[128*384];   /* W_phi2^T [k][q] */
__device__ __align__(16) float g_WmsgT[64*384];   /* W_msg^T  [k][q] */
__device__ unsigned char g_mask[NN];

/* -------- packed f32x2 helpers (.b64 regs via "l") -------- */
__device__ __forceinline__ u64t fma2d(u64t a, u64t b, u64t c) {
    u64t d; asm("fma.rn.f32x2 %0, %1, %2, %3;" : "=l"(d) : "l"(a), "l"(b), "l"(c));
    return d;
}
__device__ __forceinline__ u64t splat2(float x) {
    u64t d; asm("mov.b64 %0, {%1, %1};" : "=l"(d) : "r"(__float_as_uint(x)));
    return d;
}
__device__ __forceinline__ u64t fadd2(u64t a, u64t b) { return fma2d(a, splat2(1.0f), b); }
__device__ __forceinline__ u64t fmul2(u64t a, u64t b) { return fma2d(a, b, splat2(0.0f)); }
__device__ __forceinline__ float lo2(u64t d) { return __uint_as_float((unsigned)(d & 0xffffffffull)); }
__device__ __forceinline__ float hi2(u64t d) { return __uint_as_float((unsigned)(d >> 32)); }
__device__ __forceinline__ void red4(float* p, float a, float b, float c, float d) {
    asm volatile("red.global.add.v4.f32 [%0], {%1, %2, %3, %4};"
                 :: "l"(p), "f"(a), "f"(b), "f"(c), "f"(d) : "memory");
}

/* ---------------- fused precompute ---------------- */
__global__ void k_pre(const float* __restrict__ W_i, const float* __restrict__ W_phi1,
                      const float* __restrict__ b_phi1, const float* __restrict__ W_e2d,
                      const float* __restrict__ W_rbf, const float* __restrict__ ET,
                      const float* __restrict__ virt,
                      const float* __restrict__ W_phi2, const float* __restrict__ W_msg)
{
    int b = blockIdx.x;
    int t = threadIdx.x;
    if (b < 194) {
        int idx = b*256 + t;
        if (idx < NN) g_mask[idx] = 0;
        if (idx < 32768) {
            int k = idx >> 7, p = idx & 127;
            float s = 0.f;
            #pragma unroll 4
            for (int j = 0; j < 128; j++) s += W_phi1[p*288 + j] * W_i[j*256 + k];
            g_WcT[idx] = s;
        } else if (idx < 40960) {
            int i = idx - 32768; int k = i >> 7, p = i & 127;
            float s = 0.f;
            #pragma unroll 4
            for (int j = 0; j < 128; j++) s += W_phi1[p*288 + 128 + j] * W_e2d[j*64 + k];
            g_Wc2dT[i] = s;
        } else if (idx < 49152) {
            int i = idx - 40960; int k = i >> 7, p = i & 127;
            float s = 0.f;
            #pragma unroll 4
            for (int j = 0; j < 128; j++) s += W_phi1[p*288 + 128 + j] * W_rbf[j*64 + k];
            g_WcrbfT[i] = s;
        } else if (idx < 49536) {
            int i = idx - 49152; int tt = i >> 7, p = i & 127;
            float s = b_phi1[p];
            #pragma unroll
            for (int l = 0; l < 32; l++) s += W_phi1[p*288 + 256 + l] * ET[tt*32 + l];
            g_etb[i] = s;
        }
    } else if (b == 194) {
        __shared__ float u[128];
        if (t < 128) {
            float s = 0.f;
            #pragma unroll 4
            for (int j = 0; j < 128; j++) s += W_i[t*256 + 128 + j] * virt[j];
            u[t] = s;
        }
        __syncthreads();
        if (t < 128) {
            float c = 0.f;
            #pragma unroll 4
            for (int q = 0; q < 128; q++) c += W_phi1[t*288 + q] * u[q];
            g_cvec[t] = c;
        }
    } else {
        int idx = (b - 195)*256 + t;
        if (idx < 128*384) {
            int k = idx / 384, q = idx % 384;
            g_Wp2T[idx] = W_phi2[(size_t)q*128 + k];
        } else {
            int j = idx - 128*384;
            if (j < 64*384) {
                int k = j / 384, q = j % 384;
                g_WmsgT[j] = W_msg[(size_t)q*64 + k];
            }
        }
    }
}

__global__ void k_maskset(const int* __restrict__ Edist_idx)
{
    int idx = blockIdx.x*256 + threadIdx.x;
    if (idx < 2*E2C) g_mask[Edist_idx[idx]] = 1;
}

/* ---------------- node projection ---------------- */
__global__ void __launch_bounds__(128) k_nproj(const float* __restrict__ H,
                                               const float* __restrict__ H2d)
{
    __shared__ float hx[16*128];
    __shared__ float h2[16*128];
    int t = threadIdx.x;
    int i0 = blockIdx.x * 16;
    #pragma unroll
    for (int it = 0; it < 16; it++) {
        int idx = t + it*128;
        int nd = idx >> 7, p = idx & 127;
        hx[idx] = H  [(size_t)(i0+nd)*128 + p];
        h2[idx] = H2d[(size_t)(i0+nd)*128 + p];
    }
    __syncthreads();
    float a1[16], a2[16];
    #pragma unroll
    for (int nd = 0; nd < 16; nd++) { a1[nd] = 0.f; a2[nd] = 0.f; }
    for (int kk = 0; kk < 128; kk += 4) {
        float w0 = g_WcT[(kk+0)*128+t], w1 = g_WcT[(kk+1)*128+t];
        float w2 = g_WcT[(kk+2)*128+t], w3 = g_WcT[(kk+3)*128+t];
        float v0 = g_WcT[(128+kk+0)*128+t], v1 = g_WcT[(128+kk+1)*128+t];
        float v2 = g_WcT[(128+kk+2)*128+t], v3 = g_WcT[(128+kk+3)*128+t];
        #pragma unroll
        for (int nd = 0; nd < 16; nd++) {
            float4 f = *(const float4*)&hx[nd*128 + kk];
            a1[nd] += f.x*w0 + f.y*w1 + f.z*w2 + f.w*w3;
            float4 g = *(const float4*)&h2[nd*128 + kk];
            a2[nd] += g.x*v0 + g.y*v1 + g.z*v2 + g.w*v3;
        }
    }
    float cv = g_cvec[t];
    #pragma unroll
    for (int nd = 0; nd < 16; nd++) {
        g_nproj[(size_t)(i0+nd)*128 + t]    = a1[nd] + a2[nd];
        g_nproj[(size_t)(NN+i0+nd)*128 + t] = a1[nd] + cv;
    }
}

/* ------- GEMM micro-kernel: weights LDG-direct, 2 quads x 4 edges, K=64 ------- */
__device__ __forceinline__ void gemm64g(const float* __restrict__ W, int ldw,
                                        const float* __restrict__ xsp,
                                        int c0, int c1, u64t (&acc)[4][4])
{
    #pragma unroll 2
    for (int k4 = 0; k4 < 64; k4 += 4) {
        float4 xv[4];
        #pragma unroll
        for (int j = 0; j < 4; j++)
            xv[j] = *(const float4*)(xsp + j*(4*XSL) + k4);
        #pragma unroll
        for (int kk = 0; kk < 4; kk++) {
            ulonglong2 wA = *(const ulonglong2*)(W + (size_t)(k4+kk)*ldw + c0);
            ulonglong2 wB = *(const ulonglong2*)(W + (size_t)(k4+kk)*ldw + c1);
            #pragma unroll
            for (int j = 0; j < 4; j++) {
                u64t a = splat2(((const float*)&xv[j])[kk]);
                acc[0][j] = fma2d(a, wA.x, acc[0][j]);
                acc[1][j] = fma2d(a, wA.y, acc[1][j]);
                acc[2][j] = fma2d(a, wB.x, acc[2][j]);
                acc[3][j] = fma2d(a, wB.y, acc[3][j]);
            }
        }
    }
}

/* ---------------- fused per-edge kernel: 32 edges / 128 threads ---------------- */
__global__ void __launch_bounds__(128, 3) k_edge(
    const int* __restrict__ E2d_idx, const float* __restrict__ E2d_feat,
    const int* __restrict__ Edist_idx, const float* __restrict__ Edist_val,
    const float* __restrict__ Z, const float* __restrict__ Z3d,
    const float* __restrict__ V,
    const float* __restrict__ b_phi2, const float* __restrict__ b_msg,
    float* __restrict__ out)
{
    extern __shared__ float sm[];
    float* smxs = sm;                       /* 32 x 196 */
    int*   srow = (int*)(sm + 32*XSL);
    int*   scol = srow + 32;
    float* sdist = (float*)(scol + 32);
    float* senvd = sdist + 32;
    float* sdval = senvd + 32;
    float* senv2 = sdval + 32;
    float* sunit = senv2 + 32;              /* 32 x 3 */

    int t  = threadIdx.x;
    int w  = t >> 5;
    int l  = t & 31;
    int tp = l & 7;
    int te = l >> 3;                /* 0..3 */
    int cb = (w & 1) * 64;
    int eb = (w >> 1) * 16;
    int c0 = cb + tp*4;
    int c1 = cb + 32 + tp*4;
    int ebte = eb + te;             /* thread edges: ebte + 4*j */

    int bid = blockIdx.x;
    int base = bid * 32;
    int type = (bid < NB0) ? 0 : (bid < NB0+NB1 ? 1 : 2);

    /* --- metadata + geometry (warp 0) --- */
    if (t < 32) {
        int eg = base + t;
        int row, col; float dval = 0.f;
        if (type == 0)      { row = E2d_idx[eg]; col = E2d_idx[E1C + eg]; }
        else if (type == 1) { int i = eg - E1C; row = i; col = NN + i; }
        else                { int j = eg - E1C - NN; row = Edist_idx[j];
                              col = Edist_idx[E2C + j]; dval = Edist_val[j]; }
        srow[t] = row; scol[t] = col; sdval[t] = dval;
        float zr0 = Z[row*3+0], zr1 = Z[row*3+1], zr2 = Z[row*3+2];
        float zc0, zc1, zc2;
        if (col < NN) { zc0 = Z[col*3+0]; zc1 = Z[col*3+1]; zc2 = Z[col*3+2]; }
        else { int c2 = col - NN; zc0 = Z3d[c2*3+0]; zc1 = Z3d[c2*3+1]; zc2 = Z3d[c2*3+2]; }
        float r0 = zr0-zc0, r1 = zr1-zc1, r2 = zr2-zc2;
        float d = sqrtf(r0*r0 + r1*r1 + r2*r2 + 1e-8f);
        sdist[t] = d;
        float inv = 1.0f / d;
        sunit[t*3+0] = r0*inv; sunit[t*3+1] = r1*inv; sunit[t*3+2] = r2*inv;
        float cl = fminf(d * (1.0f/CUTV), 1.0f);
        senvd[t] = 0.5f * (cosf(PI_F*cl) + 1.0f);
        float cl2 = fminf(fmaxf(dval * (1.0f/CUTV), 0.f), 1.0f);
        senv2[t] = 0.5f * (cosf(PI_F*cl2) + 1.0f);
    }
    __syncthreads();

    /* --- per-edge 64-dim features into xs[e][128..191] --- */
    const float cstep = CUTV / 63.0f;
    const float i2w2  = 1.0f / (2.0f * (CUTV/64.0f) * (CUTV/64.0f));
    if (type == 0) {
        #pragma unroll
        for (int it = 0; it < 16; it++) {
            int idx = t + it*128; int e = idx & 31, k = idx >> 5;
            smxs[e*XSL + 128 + k] = E2d_feat[(size_t)k*E1C + base + e];
        }
    } else if (type == 2) {
        #pragma unroll
        for (int it = 0; it < 16; it++) {
            int idx = t + it*128; int e = idx & 31, k = idx >> 5;
            float diff = sdval[e] - k*cstep;
            smxs[e*XSL + 128 + k] = expf(-diff*diff*i2w2) * senv2[e];
        }
    }
    /* --- gather node projection + edge-type bias --- */
    u64t gn[4][4];
    #pragma unroll
    for (int j = 0; j < 4; j++) {
        const float* np = g_nproj + (size_t)scol[ebte + 4*j]*128;
        ulonglong2 ga = *(const ulonglong2*)(np + c0);
        ulonglong2 gb = *(const ulonglong2*)(np + c1);
        gn[0][j] = ga.x; gn[1][j] = ga.y; gn[2][j] = gb.x; gn[3][j] = gb.y;
    }
    u64t et2[4];
    {
        ulonglong2 ea = *(const ulonglong2*)(g_etb + type*128 + c0);
        ulonglong2 eb2 = *(const ulonglong2*)(g_etb + type*128 + c1);
        et2[0] = ea.x; et2[1] = ea.y; et2[2] = eb2.x; et2[3] = eb2.y;
    }
    __syncthreads();

    /* --- phase A: act = nproj[col] + etb (+ feats @ Wtype^T); silu --- */
    {
        u64t acc[4][4] = {};
        if (type == 0)
            gemm64g(g_Wc2dT, 128, smxs + ebte*XSL + 128, c0, c1, acc);
        else if (type == 2)
            gemm64g(g_WcrbfT, 128, smxs + ebte*XSL + 128, c0, c1, acc);
        #pragma unroll
        for (int j = 0; j < 4; j++) {
            int e = ebte + 4*j;
            float v[8];
            #pragma unroll
            for (int q = 0; q < 4; q++) {
                u64t s = fadd2(acc[q][j], fadd2(gn[q][j], et2[q]));
                float a = lo2(s), b = hi2(s);
                v[2*q]   = a / (1.0f + expf(-a));
                v[2*q+1] = b / (1.0f + expf(-b));
            }
            *(float4*)&smxs[e*XSL + c0] = make_float4(v[0], v[1], v[2], v[3]);
            *(float4*)&smxs[e*XSL + c1] = make_float4(v[4], v[5], v[6], v[7]);
        }
    }
    __syncthreads();

    /* --- geometric RBF overwrites feats --- */
    #pragma unroll
    for (int it = 0; it < 16; it++) {
        int idx = t + it*128; int e = idx & 31, k = idx >> 5;
        float diff = sdist[e] - k*cstep;
        smxs[e*XSL + 128 + k] = expf(-diff*diff*i2w2) * senvd[e];
    }
    __syncthreads();

    /* --- phase C (sync-free): qc order {1,2,0} --- */
    u64t vg2[4][4];
    #pragma unroll 1
    for (int qi = 0; qi < 3; qi++) {
        int qc = (qi == 0) ? 1 : (qi == 1 ? 2 : 0);
        u64t accp[4][4] = {};
        gemm64g(g_Wp2T + qc*128,            384, smxs + ebte*XSL,       c0, c1, accp);
        gemm64g(g_Wp2T + 64*384 + qc*128,   384, smxs + ebte*XSL + 64,  c0, c1, accp);
        u64t accw[4][4] = {};
        gemm64g(g_WmsgT + qc*128,           384, smxs + ebte*XSL + 128, c0, c1, accw);

        u64t bpp[4], bmm[4];
        {
            ulonglong2 a = *(const ulonglong2*)(b_phi2 + qc*128 + c0);
            ulonglong2 b = *(const ulonglong2*)(b_phi2 + qc*128 + c1);
            bpp[0] = a.x; bpp[1] = a.y; bpp[2] = b.x; bpp[3] = b.y;
            ulonglong2 c = *(const ulonglong2*)(b_msg + qc*128 + c0);
            ulonglong2 d = *(const ulonglong2*)(b_msg + qc*128 + c1);
            bmm[0] = c.x; bmm[1] = c.y; bmm[2] = d.x; bmm[3] = d.y;
        }
        u64t m2[4][4];
        #pragma unroll
        for (int q = 0; q < 4; q++)
            #pragma unroll
            for (int j = 0; j < 4; j++)
                m2[q][j] = fmul2(fadd2(accp[q][j], bpp[q]),
                                 fadd2(accw[q][j], bmm[q]));

        if (qc == 1) {
            #pragma unroll
            for (int q = 0; q < 4; q++)
                #pragma unroll
                for (int j = 0; j < 4; j++)
                    vg2[q][j] = m2[q][j];
        } else if (qc == 2) {
            #pragma unroll
            for (int j = 0; j < 4; j++) {
                int e = ebte + 4*j;
                int row = srow[e], col = scol[e];
                float u0 = sunit[e*3+0], u1 = sunit[e*3+1], u2 = sunit[e*3+2];
                float vb[24];
                if (type != 1) {
                    const float4* vpa = (const float4*)(V + (size_t)col*384 + c0*3);
                    const float4* vpb = (const float4*)(V + (size_t)col*384 + c1*3);
                    #pragma unroll
                    for (int q = 0; q < 3; q++) { ((float4*)vb)[q] = vpa[q]; ((float4*)vb)[3+q] = vpb[q]; }
                } else {
                    #pragma unroll
                    for (int q = 0; q < 24; q++) vb[q] = 0.f;
                }
                float dv[24];
                #pragma unroll
                for (int h = 0; h < 2; h++) {        /* h=0: quad c0, h=1: quad c1 */
                    #pragma unroll
                    for (int cq = 0; cq < 4; cq++) {
                        u64t vgw = vg2[h*2 + (cq>>1)][j];
                        u64t rgw = m2 [h*2 + (cq>>1)][j];
                        float vg = (cq & 1) ? hi2(vgw) : lo2(vgw);
                        float rg = (cq & 1) ? hi2(rgw) : lo2(rgw);
                        int b = h*12 + cq*3;
                        dv[b+0] = vb[b+0]*vg + u0*rg;
                        dv[b+1] = vb[b+1]*vg + u1*rg;
                        dv[b+2] = vb[b+2]*vg + u2*rg;
                    }
                }
                float* opa = out + HN + (size_t)row*384 + c0*3;
                float* opb = out + HN + (size_t)row*384 + c1*3;
                #pragma unroll
                for (int q = 0; q < 3; q++) {
                    red4(opa + q*4, dv[q*4+0],    dv[q*4+1],    dv[q*4+2],    dv[q*4+3]);
                    red4(opb + q*4, dv[12+q*4+0], dv[12+q*4+1], dv[12+q*4+2], dv[12+q*4+3]);
                }
            }
        } else { /* qc == 0 : H scatter */
            #pragma unroll
            for (int j = 0; j < 4; j++) {
                float* hp = out + (size_t)srow[ebte + 4*j]*128;
                red4(hp + c0, lo2(m2[0][j]), hi2(m2[0][j]), lo2(m2[1][j]), hi2(m2[1][j]));
                red4(hp + c1, lo2(m2[2][j]), hi2(m2[2][j]), lo2(m2[3][j]), hi2(m2[3][j]));
            }
        }
    }
}

/* ---------------- finalize ---------------- */
__global__ void k_fin(float* __restrict__ out,
                      const unsigned char* __restrict__ m2d,
                      const unsigned char* __restrict__ m3d, int total)
{
    int idx = blockIdx.x*256 + threadIdx.x;
    if (idx >= total) return;
    int i = (idx < HN) ? (idx >> 7) : ((idx - HN) / 384);
    float v = out[idx];
    v = fminf(fmaxf(v, -100.f), 100.f);
    bool keep = ((m2d[i] | m3d[i] | g_mask[i]) != 0);
    out[idx] = keep ? v : 0.f;
}

#define SMEM_EDGE ((32*XSL + 2*32 + 4*32 + 96 + 32) * sizeof(float))

extern "C" void kernel_launch(void* const* d_in, const int* in_sizes, int n_in,
                              void* d_out, int out_size)
{
    int o = (in_sizes[3] == 1) ? 1 : 0;
    const float* H      = (const float*)d_in[0];
    const float* V      = (const float*)d_in[1];
    const float* Z      = (const float*)d_in[2];
    const float* H2d    = (const float*)d_in[3+o];
    const unsigned char* m2d = (const unsigned char*)d_in[4+o];
    const int*   E2didx = (const int*)d_in[5+o];
    const float* E2dfeat= (const float*)d_in[6+o];
    const float* Z3d    = (const float*)d_in[7+o];
    const unsigned char* m3d = (const unsigned char*)d_in[8+o];
    const int*   Edidx  = (const int*)d_in[9+o];
    const float* Edval  = (const float*)d_in[10+o];
    const float* virt   = (const float*)d_in[11+o];
    const float* ETe    = (const float*)d_in[12+o];
    const float* Wrbf   = (const float*)d_in[13+o];
    const float* We2d   = (const float*)d_in[14+o];
    const float* Wi     = (const float*)d_in[15+o];
    const float* Wphi1  = (const float*)d_in[16+o];
    const float* bphi1  = (const float*)d_in[17+o];
    const float* Wphi2  = (const float*)d_in[18+o];
    const float* bphi2  = (const float*)d_in[19+o];
    const float* Wmsg   = (const float*)d_in[20+o];
    const float* bmsg   = (const float*)d_in[21+o];
    float* out = (float*)d_out;

    cudaMemsetAsync(d_out, 0, (size_t)out_size * sizeof(float));
    k_pre<<<483, 256>>>(Wi, Wphi1, bphi1, We2d, Wrbf, ETe, virt, Wphi2, Wmsg);
    k_maskset<<<782, 256>>>(Edidx);
    k_nproj<<<1250, 128>>>(H, H2d);
    cudaFuncSetAttribute(k_edge, cudaFuncAttributeMaxDynamicSharedMemorySize,
                         (int)SMEM_EDGE);
    k_edge<<<NBT, 128, SMEM_EDGE>>>(E2didx, E2dfeat, Edidx, Edval, Z, Z3d, V,
                                    bphi2, bmsg, out);
    k_fin<<<(HN + 3*HN + 255)/256, 256>>>(out, m2d, m3d, HN + 3*HN);
}